// round 6
// baseline (speedup 1.0000x reference)
#include <cuda_runtime.h>
#include <cstdint>

#define R_BINS 64
#define Z_BINS 64
#define NBINS (R_BINS * Z_BINS)
#define NTHREADS 512
#define NBLOCKS (148 * 3)
#define TILE_GROUPS 512                      // groups (4 pts each) per tile
#define TILE_POSBYTES (TILE_GROUPS * 48)     // 24576 B of positions per tile

// Dynamic smem layout
#define SM_POS0   0
#define SM_POS1   (TILE_POSBYTES)
#define SM_HIST   (2 * TILE_POSBYTES)                    // 49152
#define SM_MBAR   (SM_HIST + NBINS * 4)                  // 65536
#define SM_FLAG   (SM_MBAR + 16)
#define SMEM_TOTAL (SM_FLAG + 16)

__device__ float g_hist[NBINS];          // zeroed at load; kernel leaves it zeroed
__device__ unsigned int g_ticket;

static __device__ __forceinline__ uint32_t s2u(const void* p) {
    return (uint32_t)__cvta_generic_to_shared(p);
}

static __device__ __forceinline__ void mbar_init(uint32_t mbar, uint32_t cnt) {
    asm volatile("mbarrier.init.shared.b64 [%0], %1;" :: "r"(mbar), "r"(cnt) : "memory");
}
static __device__ __forceinline__ void mbar_expect_tx(uint32_t mbar, uint32_t bytes) {
    asm volatile("mbarrier.arrive.expect_tx.shared.b64 _, [%0], %1;" :: "r"(mbar), "r"(bytes) : "memory");
}
static __device__ __forceinline__ void bulk_g2s(uint32_t dst, const void* src, uint32_t bytes, uint32_t mbar) {
    asm volatile("cp.async.bulk.shared::cta.global.mbarrier::complete_tx::bytes [%0], [%1], %2, [%3];"
                 :: "r"(dst), "l"(src), "r"(bytes), "r"(mbar) : "memory");
}
static __device__ __forceinline__ void mbar_wait(uint32_t mbar, uint32_t parity) {
    uint32_t done;
    do {
        asm volatile("{\n\t.reg .pred p;\n\t"
                     "mbarrier.try_wait.parity.acquire.cta.shared::cta.b64 p, [%1], %2, 0x989680;\n\t"
                     "selp.b32 %0, 1, 0, p;\n\t}"
                     : "=r"(done) : "r"(mbar), "r"(parity) : "memory");
    } while (!done);
}

static __device__ __forceinline__ void bin_point(float* sh, float x, float y, float z, float m) {
    const float INV_DR = 6.4f;
    const float INV_DZ = 16.0f;
    const float Z_MINf = -2.0f;
    float r2 = fmaxf(x * x + y * y, 1e-30f);
    float r = r2 * rsqrtf(r2);                 // ~2ulp sqrt
    int i = (int)(r * INV_DR);
    int j = (int)floorf((z - Z_MINf) * INV_DZ);
    if (((unsigned)i < R_BINS) & ((unsigned)j < Z_BINS)) {
        atomicAdd(sh + (i << 6) + j, m);
    }
}

__global__ void __launch_bounds__(NTHREADS, 3)
fused_hist_kernel(const float4* __restrict__ pos4,
                  const float4* __restrict__ mass4,
                  int ngroups,
                  float* __restrict__ out) {
    extern __shared__ char smem[];
    float* sh = (float*)(smem + SM_HIST);
    int* s_flag = (int*)(smem + SM_FLAG);
    uint32_t mbar0 = s2u(smem + SM_MBAR);
    const int tid = threadIdx.x;

    for (int i = tid; i < NBINS; i += NTHREADS) sh[i] = 0.0f;
    if (tid == 0) {
        mbar_init(mbar0, 1);
        mbar_init(mbar0 + 8, 1);
        asm volatile("fence.proxy.async.shared::cta;" ::: "memory");
    }
    __syncthreads();

    const int ntiles = ngroups / TILE_GROUPS;
    const int tstride = gridDim.x;

    // Prologue: fill both pipeline stages.
    if (tid == 0) {
        if (blockIdx.x < ntiles) {
            mbar_expect_tx(mbar0, TILE_POSBYTES);
            bulk_g2s(s2u(smem + SM_POS0), pos4 + 3 * (size_t)blockIdx.x * TILE_GROUPS,
                     TILE_POSBYTES, mbar0);
        }
        if (blockIdx.x + tstride < ntiles) {
            mbar_expect_tx(mbar0 + 8, TILE_POSBYTES);
            bulk_g2s(s2u(smem + SM_POS1), pos4 + 3 * (size_t)(blockIdx.x + tstride) * TILE_GROUPS,
                     TILE_POSBYTES, mbar0 + 8);
        }
    }

    int it = 0;
    for (int t = blockIdx.x; t < ntiles; t += tstride, it++) {
        int buf = it & 1;
        uint32_t ph = (uint32_t)(it >> 1) & 1u;

        // Prefetch this tile's masses (independent LDG, overlaps the wait).
        float4 m = mass4[(size_t)t * TILE_GROUPS + tid];

        mbar_wait(mbar0 + 8 * buf, ph);

        // 48B per thread from smem: 3x LDS.128 at stride 48 -> conflict-free.
        const char* pbase = smem + (buf ? SM_POS1 : SM_POS0) + tid * 48;
        float4 a = *(const float4*)(pbase + 0);
        float4 b = *(const float4*)(pbase + 16);
        float4 c = *(const float4*)(pbase + 32);

        bin_point(sh, a.x, a.y, a.z, m.x);
        bin_point(sh, a.w, b.x, b.y, m.y);
        bin_point(sh, b.z, b.w, c.x, m.z);
        bin_point(sh, c.y, c.z, c.w, m.w);

        __syncthreads();   // everyone done reading this buffer

        int tn = t + 2 * tstride;
        if (tid == 0 && tn < ntiles) {
            mbar_expect_tx(mbar0 + 8 * buf, TILE_POSBYTES);
            bulk_g2s(s2u(smem + (buf ? SM_POS1 : SM_POS0)),
                     pos4 + 3 * (size_t)tn * TILE_GROUPS, TILE_POSBYTES, mbar0 + 8 * buf);
        }
    }

    // Tail groups (ngroups % TILE_GROUPS), direct LDG path, block 0 only.
    if (blockIdx.x == 0) {
        for (int g = ntiles * TILE_GROUPS + tid; g < ngroups; g += NTHREADS) {
            float4 a = pos4[3 * (size_t)g + 0];
            float4 b = pos4[3 * (size_t)g + 1];
            float4 c = pos4[3 * (size_t)g + 2];
            float4 m = mass4[g];
            bin_point(sh, a.x, a.y, a.z, m.x);
            bin_point(sh, a.w, b.x, b.y, m.y);
            bin_point(sh, b.z, b.w, c.x, m.z);
            bin_point(sh, c.y, c.z, c.w, m.w);
        }
    }

    __syncthreads();
    for (int idx = tid; idx < NBINS; idx += NTHREADS) {
        float v = sh[idx];
        if (v != 0.0f) atomicAdd(&g_hist[idx], v);
    }

    __threadfence();
    if (tid == 0) {
        unsigned int tk = atomicAdd(&g_ticket, 1u);
        *s_flag = (tk == (unsigned int)(gridDim.x - 1));
    }
    __syncthreads();

    if (*s_flag) {
        const float DRf = 0.15625f;
        const float DZf = 0.0625f;
        const float PIf = 3.14159265358979f;
        for (int idx = tid; idx < NBINS; idx += NTHREADS) {
            float v = atomicExch(&g_hist[idx], 0.0f);   // coherent read + reset for next replay
            int i = idx >> 6;
            float r0 = (float)i * DRf;
            float r1 = (float)(i + 1) * DRf;
            float vol = PIf * (r1 * r1 - r0 * r0) * DZf;
            out[idx] = v / vol;
        }
        if (tid == 0) atomicExch(&g_ticket, 0u);
    }
}

extern "C" void kernel_launch(void* const* d_in, const int* in_sizes, int n_in,
                              void* d_out, int out_size) {
    const float4* pos4 = (const float4*)d_in[0];   // positions [N,3] float32
    const float4* mass4 = (const float4*)d_in[1];  // masses [N] float32
    int n = in_sizes[1];
    int ngroups = n / 4;                           // N = 2^24 -> divisible

    static bool attr_done = false;
    if (!attr_done) {
        cudaFuncSetAttribute(fused_hist_kernel,
                             cudaFuncAttributeMaxDynamicSharedMemorySize, SMEM_TOTAL);
        attr_done = true;
    }

    fused_hist_kernel<<<NBLOCKS, NTHREADS, SMEM_TOTAL>>>(pos4, mass4, ngroups, (float*)d_out);
}